// round 14
// baseline (speedup 1.0000x reference)
#include <cuda_runtime.h>
#include <cstdint>

// Shapes (fixed):
//   x[4,2048,4096] f32, eof[4] i32, noise[4,8] f32, A_w[32,4096] f32,
//   B_w[8,4096,32] f32, route_w[8,4096] f32, noise_w[8,4096] f32
//   out[4,2048,4096] f32

#define U64 unsigned long long
#define NSPLIT 16

// ---------------- scratch ----------------
__device__ float g_logits[32];
__device__ float g_At[4096 * 32];           // A transposed [k][r]
__device__ float g_Wc[4 * 4096 * 32];       // combined weight [b][o][r], 2x scaling folded
__device__ float g_part[NSPLIT][8192 * 32]; // split-K partials
__device__ float g_shared[8192 * 32];       // reduced shared activations [m][r]

// ---------------- packed f32x2 helpers ----------------
__device__ __forceinline__ U64 pk2(float v) {
    U64 r; asm("mov.b64 %0, {%1, %1};" : "=l"(r) : "f"(v)); return r;
}
__device__ __forceinline__ void ffma2(U64 &d, U64 a, U64 b) {
    asm("fma.rn.f32x2 %0, %1, %2, %0;" : "+l"(d) : "l"(a), "l"(b));
}
__device__ __forceinline__ float2 upk(U64 v) {
    float2 r; asm("mov.b64 {%0, %1}, %2;" : "=f"(r.x), "=f"(r.y) : "l"(v)); return r;
}

// ---------------- kernel 1: gating logits (32 blocks = (b,e)) ----------------
__global__ __launch_bounds__(256) void gating_logits_kernel(
    const float* __restrict__ x, const int* __restrict__ eof,
    const float* __restrict__ noise,
    const float* __restrict__ route_w, const float* __restrict__ noise_w)
{
    int be = blockIdx.x;
    int b = be >> 3, e = be & 7;
    const float* xr = x + ((size_t)b * 2048 + (size_t)eof[b]) * 4096;
    const float* rw = route_w + e * 4096;
    const float* nw = noise_w + e * 4096;

    float c = 0.f, n = 0.f;
    int t = threadIdx.x;
    for (int k = t * 4; k < 4096; k += 256 * 4) {
        float4 xv = *(const float4*)(xr + k);
        float4 rv = *(const float4*)(rw + k);
        float4 nv = *(const float4*)(nw + k);
        c += xv.x * rv.x + xv.y * rv.y + xv.z * rv.z + xv.w * rv.w;
        n += xv.x * nv.x + xv.y * nv.y + xv.z * nv.z + xv.w * nv.w;
    }
    #pragma unroll
    for (int off = 16; off; off >>= 1) {
        c += __shfl_down_sync(0xFFFFFFFFu, c, off);
        n += __shfl_down_sync(0xFFFFFFFFu, n, off);
    }
    __shared__ float sc[8], sn[8];
    if ((t & 31) == 0) { sc[t >> 5] = c; sn[t >> 5] = n; }
    __syncthreads();
    if (t == 0) {
        float cs = 0.f, ns = 0.f;
        #pragma unroll
        for (int w = 0; w < 8; w++) { cs += sc[w]; ns += sn[w]; }
        float sp = (ns > 20.f) ? ns : log1pf(expf(ns));
        g_logits[be] = cs + noise[b * 8 + e] * (sp + 0.01f);
    }
}

// ---------------- kernel 2: combine expert weights (top-2 gates inline) --------
__global__ __launch_bounds__(256) void combine_w_kernel(const float* __restrict__ Bw)
{
    int idx = blockIdx.x * 256 + threadIdx.x;   // float4 index, 0..131071
    int b = idx >> 15;
    int rem4 = idx & 32767;

    float v[8];
    #pragma unroll
    for (int e = 0; e < 8; e++) v[e] = g_logits[b * 8 + e];
    int i1 = 0;
    #pragma unroll
    for (int e = 1; e < 8; e++) if (v[e] > v[i1]) i1 = e;
    int i2 = (i1 == 0) ? 1 : 0;
    #pragma unroll
    for (int e = 0; e < 8; e++) if (e != i1 && v[e] > v[i2]) i2 = e;
    float e2 = expf(v[i2] - v[i1]);
    float inv = 2.f / (1.f + e2);     // SCALING folded
    float g1 = inv;
    float g2 = e2 * inv;

    float4 p = *(const float4*)(Bw + (size_t)i1 * 131072 + (size_t)rem4 * 4);
    float4 q = *(const float4*)(Bw + (size_t)i2 * 131072 + (size_t)rem4 * 4);
    float4 acc;
    acc.x = g1 * p.x + g2 * q.x;
    acc.y = g1 * p.y + g2 * q.y;
    acc.z = g1 * p.z + g2 * q.z;
    acc.w = g1 * p.w + g2 * q.w;
    *(float4*)(g_Wc + (size_t)idx * 4) = acc;
}

// ---------------- kernel 3: transpose A [32,4096] -> [4096,32], tiled ----------
__global__ __launch_bounds__(256) void transposeA_kernel(const float* __restrict__ Aw)
{
    __shared__ float s[32][33];
    int k0 = blockIdx.x * 32;
    int lane = threadIdx.x & 31;
    int grp  = threadIdx.x >> 5;
    #pragma unroll
    for (int i = 0; i < 4; i++) {
        int r = grp + i * 8;
        s[r][lane] = Aw[r * 4096 + k0 + lane];
    }
    __syncthreads();
    #pragma unroll
    for (int i = 0; i < 4; i++) {
        int kk = grp + i * 8;
        g_At[(k0 + kk) * 32 + lane] = s[lane][kk];
    }
}

// ---------------- kernel 4: GEMM1 split-K (R10-proven, unchanged) ----------
// part[s][m][r] = sum_{k in 256-chunk} x[m][k] * At[k][r]
// grid = (64 m-tiles, NSPLIT), block = 128. BM=128, BK=32, micro 8m x 4r.
#define XST 132
__global__ __launch_bounds__(128) void gemm1_kernel(const float* __restrict__ x)
{
    __shared__ __align__(16) float Xs[32 * XST];  // [k][m], 16.9KB
    __shared__ __align__(16) float As[32 * 32];   // [k][r], 4KB

    int tid = threadIdx.x;
    int mbase = blockIdx.x * 128;
    int kbase = blockIdx.y * (4096 / NSPLIT);     // 256-k chunk = 8 tiles of 32

    int lrow  = tid >> 3;           // 0..15 ; X rows = lrow + 16*j
    int klane = tid & 7;            // thread's k set: klane + 8*i
    const float* xt = x + (size_t)(mbase + lrow) * 4096 + kbase + klane;
    const float* ag = g_At + (size_t)kbase * 32;

    // prologue: LDG tile 0 into registers (scalar, 4-sector coalesced)
    float xr[8][4];
    float4 ar[2];
    #pragma unroll
    for (int j = 0; j < 8; j++)
        #pragma unroll
        for (int i = 0; i < 4; i++)
            xr[j][i] = xt[(size_t)(16 * j) * 4096 + 8 * i];
    #pragma unroll
    for (int j = 0; j < 2; j++)
        ar[j] = *(const float4*)(ag + (tid + 128 * j) * 4);

    int m0 = (tid >> 3) * 8;        // 0..120
    int r0 = (tid & 7) * 4;         // 0..28

    U64 acc[4][4];
    #pragma unroll
    for (int p = 0; p < 4; p++)
        #pragma unroll
        for (int rr = 0; rr < 4; rr++) acc[p][rr] = 0;

    #pragma unroll 1
    for (int t = 0; t < 8; t++) {
        __syncthreads();            // previous compute done before overwrite
        // STS: conflict-free transposed stores (bank = 4*(tid&7)+lrow)
        #pragma unroll
        for (int i = 0; i < 4; i++) {
            int kk = klane + 8 * i;
            #pragma unroll
            for (int j = 0; j < 8; j++)
                Xs[kk * XST + lrow + 16 * j] = xr[j][i];
        }
        #pragma unroll
        for (int j = 0; j < 2; j++)
            *(float4*)&As[(tid + 128 * j) * 4] = ar[j];
        __syncthreads();

        // prefetch next tile (overlaps compute)
        if (t < 7) {
            const float* xt2 = xt + (t + 1) * 32;
            const float* ag2 = ag + (t + 1) * 1024;
            #pragma unroll
            for (int j = 0; j < 8; j++)
                #pragma unroll
                for (int i = 0; i < 4; i++)
                    xr[j][i] = xt2[(size_t)(16 * j) * 4096 + 8 * i];
            #pragma unroll
            for (int j = 0; j < 2; j++)
                ar[j] = *(const float4*)(ag2 + (tid + 128 * j) * 4);
        }

        #pragma unroll
        for (int k = 0; k < 32; k++) {
            ulonglong2 sA = *(const ulonglong2*)&Xs[k * XST + m0];      // m0..m0+3
            ulonglong2 sB = *(const ulonglong2*)&Xs[k * XST + m0 + 4];  // m0+4..m0+7
            float4 av = *(const float4*)&As[k * 32 + r0];
            U64 w0 = pk2(av.x), w1 = pk2(av.y), w2 = pk2(av.z), w3 = pk2(av.w);
            ffma2(acc[0][0], sA.x, w0); ffma2(acc[1][0], sA.y, w0);
            ffma2(acc[2][0], sB.x, w0); ffma2(acc[3][0], sB.y, w0);
            ffma2(acc[0][1], sA.x, w1); ffma2(acc[1][1], sA.y, w1);
            ffma2(acc[2][1], sB.x, w1); ffma2(acc[3][1], sB.y, w1);
            ffma2(acc[0][2], sA.x, w2); ffma2(acc[1][2], sA.y, w2);
            ffma2(acc[2][2], sB.x, w2); ffma2(acc[3][2], sB.y, w2);
            ffma2(acc[0][3], sA.x, w3); ffma2(acc[1][3], sA.y, w3);
            ffma2(acc[2][3], sB.x, w3); ffma2(acc[3][3], sB.y, w3);
        }
    }

    float* op = g_part[blockIdx.y] + (size_t)mbase * 32;
    #pragma unroll
    for (int p = 0; p < 4; p++) {
        float2 u0 = upk(acc[p][0]), u1 = upk(acc[p][1]);
        float2 u2 = upk(acc[p][2]), u3 = upk(acc[p][3]);
        *(float4*)(op + (size_t)(m0 + 2 * p) * 32 + r0) =
            make_float4(u0.x, u1.x, u2.x, u3.x);
        *(float4*)(op + (size_t)(m0 + 2 * p + 1) * 32 + r0) =
            make_float4(u0.y, u1.y, u2.y, u3.y);
    }
}

// ---------------- kernel 5: reduce split-K partials ----------------
__global__ __launch_bounds__(256) void reduce_shared_kernel()
{
    int idx = blockIdx.x * 256 + threadIdx.x;   // float4 idx, 0..65535
    float4 s = *(const float4*)(g_part[0] + (size_t)idx * 4);
    #pragma unroll
    for (int p = 1; p < NSPLIT; p++) {
        float4 a = *(const float4*)(g_part[p] + (size_t)idx * 4);
        s.x += a.x; s.y += a.y; s.z += a.z; s.w += a.w;
    }
    *(float4*)(g_shared + (size_t)idx * 4) = s;
}

// ---------------- kernel 6: GEMM2, tile 256m x 64o, 256 threads, micro 8m x 8o
// out[b][m][o] = sum_r shared[b*2048+m][r] * Wc[b][o][r]
// S loader = R4 pattern per 128-row half; W loader = R4 pattern verbatim.
#define G2ST 260
__global__ __launch_bounds__(256) void gemm2_kernel(float* __restrict__ out)
{
    __shared__ __align__(16) float Ss[32 * G2ST];  // [k][m], m=256, 33.3KB
    __shared__ __align__(16) float Ws[32 * 68];    // [k][o], o=64,  8.7KB

    int tid = threadIdx.x;
    int b = blockIdx.z;
    int mbase = blockIdx.y * 256;
    int obase = blockIdx.x * 64;

    const float* sg = g_shared + ((size_t)b * 2048 + mbase) * 32;
    const float* wg = g_Wc + ((size_t)b * 4096 + obase) * 32;

    // load S: 256 rows x 32 k -> Ss[k][m]  (two 128-row halves, R4 mapping)
    {
        int row = tid >> 1;
        int k0 = (tid & 1) * 16;
        #pragma unroll
        for (int h = 0; h < 2; h++) {
            int r = row + 128 * h;
            const float* p = sg + (size_t)r * 32 + k0;
            #pragma unroll
            for (int q = 0; q < 4; q++) {
                float4 v = *(const float4*)(p + 4 * q);
                Ss[(k0 + 4 * q + 0) * G2ST + r] = v.x;
                Ss[(k0 + 4 * q + 1) * G2ST + r] = v.y;
                Ss[(k0 + 4 * q + 2) * G2ST + r] = v.z;
                Ss[(k0 + 4 * q + 3) * G2ST + r] = v.w;
            }
        }
    }
    // load W: 64 rows x 32 k -> Ws[k][o]  (R4 pattern)
    {
        int row = tid >> 2;
        int k0 = (tid & 3) * 8;
        const float* p = wg + row * 32 + k0;
        float4 w0 = *(const float4*)(p);
        float4 w1 = *(const float4*)(p + 4);
        Ws[(k0 + 0) * 68 + row] = w0.x;
        Ws[(k0 + 1) * 68 + row] = w0.y;
        Ws[(k0 + 2) * 68 + row] = w0.z;
        Ws[(k0 + 3) * 68 + row] = w0.w;
        Ws[(k0 + 4) * 68 + row] = w1.x;
        Ws[(k0 + 5) * 68 + row] = w1.y;
        Ws[(k0 + 6) * 68 + row] = w1.z;
        Ws[(k0 + 7) * 68 + row] = w1.w;
    }
    __syncthreads();

    int m0 = (tid >> 3) * 8;    // 0..248
    int o0 = (tid & 7) * 8;     // 0..56

    U64 acc[4][8];              // [m-pair p][o0+q]
    #pragma unroll
    for (int p = 0; p < 4; p++)
        #pragma unroll
        for (int q = 0; q < 8; q++) acc[p][q] = 0;

    #pragma unroll
    for (int k = 0; k < 32; k++) {
        ulonglong2 sA = *(const ulonglong2*)&Ss[k * G2ST + m0];      // m0..m0+3
        ulonglong2 sB = *(const ulonglong2*)&Ss[k * G2ST + m0 + 4];  // m0+4..m0+7
        float4 a0 = *(const float4*)&Ws[k * 68 + o0];
        float4 a1 = *(const float4*)&Ws[k * 68 + o0 + 4];
        U64 w0 = pk2(a0.x), w1 = pk2(a0.y), w2 = pk2(a0.z), w3 = pk2(a0.w);
        U64 w4 = pk2(a1.x), w5 = pk2(a1.y), w6 = pk2(a1.z), w7 = pk2(a1.w);
        ffma2(acc[0][0], sA.x, w0); ffma2(acc[1][0], sA.y, w0);
        ffma2(acc[2][0], sB.x, w0); ffma2(acc[3][0], sB.y, w0);
        ffma2(acc[0][1], sA.x, w1); ffma2(acc[1][1], sA.y, w1);
        ffma2(acc[2][1], sB.x, w1); ffma2(acc[3][1], sB.y, w1);
        ffma2(acc[0][2], sA.x, w2); ffma2(acc[1][2], sA.y, w2);
        ffma2(acc[2][2], sB.x, w2); ffma2(acc[3][2], sB.y, w2);
        ffma2(acc[0][3], sA.x, w3); ffma2(acc[1][3], sA.y, w3);
        ffma2(acc[2][3], sB.x, w3); ffma2(acc[3][3], sB.y, w3);
        ffma2(acc[0][4], sA.x, w4); ffma2(acc[1][4], sA.y, w4);
        ffma2(acc[2][4], sB.x, w4); ffma2(acc[3][4], sB.y, w4);
        ffma2(acc[0][5], sA.x, w5); ffma2(acc[1][5], sA.y, w5);
        ffma2(acc[2][5], sB.x, w5); ffma2(acc[3][5], sB.y, w5);
        ffma2(acc[0][6], sA.x, w6); ffma2(acc[1][6], sA.y, w6);
        ffma2(acc[2][6], sB.x, w6); ffma2(acc[3][6], sB.y, w6);
        ffma2(acc[0][7], sA.x, w7); ffma2(acc[1][7], sA.y, w7);
        ffma2(acc[2][7], sB.x, w7); ffma2(acc[3][7], sB.y, w7);
    }

    #pragma unroll
    for (int p = 0; p < 4; p++) {
        float2 u0 = upk(acc[p][0]), u1 = upk(acc[p][1]);
        float2 u2 = upk(acc[p][2]), u3 = upk(acc[p][3]);
        float2 u4 = upk(acc[p][4]), u5 = upk(acc[p][5]);
        float2 u6 = upk(acc[p][6]), u7 = upk(acc[p][7]);
        float* r0p = out + ((size_t)(b * 2048 + mbase + m0 + 2 * p)) * 4096 + obase + o0;
        float* r1p = r0p + 4096;
        *(float4*)(r0p)     = make_float4(u0.x, u1.x, u2.x, u3.x);
        *(float4*)(r0p + 4) = make_float4(u4.x, u5.x, u6.x, u7.x);
        *(float4*)(r1p)     = make_float4(u0.y, u1.y, u2.y, u3.y);
        *(float4*)(r1p + 4) = make_float4(u4.y, u5.y, u6.y, u7.y);
    }
}

// ---------------- launch ----------------
extern "C" void kernel_launch(void* const* d_in, const int* in_sizes, int n_in,
                              void* d_out, int out_size)
{
    const float* x     = (const float*)d_in[0];
    const int*   eof   = (const int*)  d_in[1];
    const float* noise = (const float*)d_in[2];
    const float* Aw    = (const float*)d_in[3];
    const float* Bw    = (const float*)d_in[4];
    const float* rw    = (const float*)d_in[5];
    const float* nw    = (const float*)d_in[6];
    float* out = (float*)d_out;

    gating_logits_kernel<<<32, 256>>>(x, eof, noise, rw, nw);
    transposeA_kernel<<<128, 256>>>(Aw);
    combine_w_kernel<<<512, 256>>>(Bw);
    gemm1_kernel<<<dim3(64, NSPLIT), 128>>>(x);
    reduce_shared_kernel<<<256, 256>>>();
    gemm2_kernel<<<dim3(64, 8, 4), 256>>>(out);
}

// round 15
// speedup vs baseline: 1.0138x; 1.0138x over previous
#include <cuda_runtime.h>
#include <cstdint>

// Shapes (fixed):
//   x[4,2048,4096] f32, eof[4] i32, noise[4,8] f32, A_w[32,4096] f32,
//   B_w[8,4096,32] f32, route_w[8,4096] f32, noise_w[8,4096] f32
//   out[4,2048,4096] f32

#define U64 unsigned long long
#define NSPLIT 16

// ---------------- scratch ----------------
__device__ float g_logits[32];
__device__ float g_At[4096 * 32];           // A transposed [k][r]
__device__ float g_Wc[4 * 4096 * 32];       // combined weight [b][o][r], 2x scaling folded
__device__ float g_part[NSPLIT][8192 * 32]; // split-K partials
__device__ float g_shared[8192 * 32];       // reduced shared activations [m][r]

// ---------------- packed f32x2 helpers ----------------
__device__ __forceinline__ U64 pk2(float v) {
    U64 r; asm("mov.b64 %0, {%1, %1};" : "=l"(r) : "f"(v)); return r;
}
__device__ __forceinline__ void ffma2(U64 &d, U64 a, U64 b) {
    asm("fma.rn.f32x2 %0, %1, %2, %0;" : "+l"(d) : "l"(a), "l"(b));
}
__device__ __forceinline__ float2 upk(U64 v) {
    float2 r; asm("mov.b64 {%0, %1}, %2;" : "=f"(r.x), "=f"(r.y) : "l"(v)); return r;
}

// ---------------- kernel 1: gating logits (32 blocks = (b,e)) ----------------
__global__ __launch_bounds__(256) void gating_logits_kernel(
    const float* __restrict__ x, const int* __restrict__ eof,
    const float* __restrict__ noise,
    const float* __restrict__ route_w, const float* __restrict__ noise_w)
{
    int be = blockIdx.x;
    int b = be >> 3, e = be & 7;
    const float* xr = x + ((size_t)b * 2048 + (size_t)eof[b]) * 4096;
    const float* rw = route_w + e * 4096;
    const float* nw = noise_w + e * 4096;

    float c = 0.f, n = 0.f;
    int t = threadIdx.x;
    for (int k = t * 4; k < 4096; k += 256 * 4) {
        float4 xv = *(const float4*)(xr + k);
        float4 rv = *(const float4*)(rw + k);
        float4 nv = *(const float4*)(nw + k);
        c += xv.x * rv.x + xv.y * rv.y + xv.z * rv.z + xv.w * rv.w;
        n += xv.x * nv.x + xv.y * nv.y + xv.z * nv.z + xv.w * nv.w;
    }
    #pragma unroll
    for (int off = 16; off; off >>= 1) {
        c += __shfl_down_sync(0xFFFFFFFFu, c, off);
        n += __shfl_down_sync(0xFFFFFFFFu, n, off);
    }
    __shared__ float sc[8], sn[8];
    if ((t & 31) == 0) { sc[t >> 5] = c; sn[t >> 5] = n; }
    __syncthreads();
    if (t == 0) {
        float cs = 0.f, ns = 0.f;
        #pragma unroll
        for (int w = 0; w < 8; w++) { cs += sc[w]; ns += sn[w]; }
        float sp = (ns > 20.f) ? ns : log1pf(expf(ns));
        g_logits[be] = cs + noise[b * 8 + e] * (sp + 0.01f);
    }
}

// ---------------- kernel 2: combine expert weights (top-2 gates inline) --------
__global__ __launch_bounds__(256) void combine_w_kernel(const float* __restrict__ Bw)
{
    int idx = blockIdx.x * 256 + threadIdx.x;   // float4 index, 0..131071
    int b = idx >> 15;
    int rem4 = idx & 32767;

    float v[8];
    #pragma unroll
    for (int e = 0; e < 8; e++) v[e] = g_logits[b * 8 + e];
    int i1 = 0;
    #pragma unroll
    for (int e = 1; e < 8; e++) if (v[e] > v[i1]) i1 = e;
    int i2 = (i1 == 0) ? 1 : 0;
    #pragma unroll
    for (int e = 0; e < 8; e++) if (e != i1 && v[e] > v[i2]) i2 = e;
    float e2 = expf(v[i2] - v[i1]);
    float inv = 2.f / (1.f + e2);     // SCALING folded
    float g1 = inv;
    float g2 = e2 * inv;

    float4 p = *(const float4*)(Bw + (size_t)i1 * 131072 + (size_t)rem4 * 4);
    float4 q = *(const float4*)(Bw + (size_t)i2 * 131072 + (size_t)rem4 * 4);
    float4 acc;
    acc.x = g1 * p.x + g2 * q.x;
    acc.y = g1 * p.y + g2 * q.y;
    acc.z = g1 * p.z + g2 * q.z;
    acc.w = g1 * p.w + g2 * q.w;
    *(float4*)(g_Wc + (size_t)idx * 4) = acc;
}

// ---------------- kernel 3: transpose A [32,4096] -> [4096,32], tiled ----------
__global__ __launch_bounds__(256) void transposeA_kernel(const float* __restrict__ Aw)
{
    __shared__ float s[32][33];
    int k0 = blockIdx.x * 32;
    int lane = threadIdx.x & 31;
    int grp  = threadIdx.x >> 5;
    #pragma unroll
    for (int i = 0; i < 4; i++) {
        int r = grp + i * 8;
        s[r][lane] = Aw[r * 4096 + k0 + lane];
    }
    __syncthreads();
    #pragma unroll
    for (int i = 0; i < 4; i++) {
        int kk = grp + i * 8;
        g_At[(k0 + kk) * 32 + lane] = s[lane][kk];
    }
}

// ---------------- kernel 4: GEMM1 split-K, micro 16m x 4r ----------
// part[s][m][r] = sum_{k in 256-chunk} x[m][k] * At[k][r]
// grid = (32 m-tiles, NSPLIT), block = 128. BM=256, BK=16.
// STS bank = 8*klane + lrow (stride 264 == 8 mod 32): all 32 lanes distinct.
#define XST1 264
__global__ __launch_bounds__(128) void gemm1_kernel(const float* __restrict__ x)
{
    __shared__ __align__(16) float Xs[16 * XST1];  // [k][m], 16.5KB
    __shared__ __align__(16) float As[16 * 32];    // [k][r], 2KB

    int tid = threadIdx.x;
    int mbase = blockIdx.x * 256;
    int kbase = blockIdx.y * (4096 / NSPLIT);      // 256-k chunk = 16 tiles of 16

    int lrow  = tid >> 2;           // 0..31 ; X rows = lrow + 32*j, j<8
    int klane = tid & 3;            // thread's k set: klane + 4*i, i<4
    const float* xt = x + (size_t)(mbase + lrow) * 4096 + kbase + klane;
    const float* ag = g_At + (size_t)kbase * 32;

    // prologue: LDG tile 0 into registers
    float xr[8][4];
    float4 ar;
    #pragma unroll
    for (int j = 0; j < 8; j++)
        #pragma unroll
        for (int i = 0; i < 4; i++)
            xr[j][i] = xt[(size_t)(32 * j) * 4096 + 4 * i];
    ar = *(const float4*)(ag + tid * 4);           // As row tid>>3, cols (tid&7)*4

    int m0 = (tid >> 3) * 16;       // 0..240
    int r0 = (tid & 7) * 4;         // 0..28

    U64 acc[8][4];                  // [m-pair p: rows m0+2p, m0+2p+1][r0+rr]
    #pragma unroll
    for (int p = 0; p < 8; p++)
        #pragma unroll
        for (int rr = 0; rr < 4; rr++) acc[p][rr] = 0;

    #pragma unroll 1
    for (int t = 0; t < 16; t++) {
        __syncthreads();            // previous compute done before overwrite
        // STS: conflict-free transposed stores (bank = 8*klane + lrow)
        #pragma unroll
        for (int i = 0; i < 4; i++) {
            int kk = klane + 4 * i;
            #pragma unroll
            for (int j = 0; j < 8; j++)
                Xs[kk * XST1 + lrow + 32 * j] = xr[j][i];
        }
        *(float4*)&As[tid * 4] = ar;
        __syncthreads();

        // prefetch next tile (overlaps compute)
        if (t < 15) {
            const float* xt2 = xt + (t + 1) * 16;
            const float* ag2 = ag + (t + 1) * 512;
            #pragma unroll
            for (int j = 0; j < 8; j++)
                #pragma unroll
                for (int i = 0; i < 4; i++)
                    xr[j][i] = xt2[(size_t)(32 * j) * 4096 + 4 * i];
            ar = *(const float4*)(ag2 + tid * 4);
        }

        #pragma unroll
        for (int k = 0; k < 16; k++) {
            ulonglong2 sA = *(const ulonglong2*)&Xs[k * XST1 + m0];      // m0..m0+3
            ulonglong2 sB = *(const ulonglong2*)&Xs[k * XST1 + m0 + 4];  // m0+4..m0+7
            ulonglong2 sC = *(const ulonglong2*)&Xs[k * XST1 + m0 + 8];  // m0+8..m0+11
            ulonglong2 sD = *(const ulonglong2*)&Xs[k * XST1 + m0 + 12]; // m0+12..m0+15
            float4 av = *(const float4*)&As[k * 32 + r0];
            U64 w0 = pk2(av.x), w1 = pk2(av.y), w2 = pk2(av.z), w3 = pk2(av.w);
            ffma2(acc[0][0], sA.x, w0); ffma2(acc[1][0], sA.y, w0);
            ffma2(acc[2][0], sB.x, w0); ffma2(acc[3][0], sB.y, w0);
            ffma2(acc[4][0], sC.x, w0); ffma2(acc[5][0], sC.y, w0);
            ffma2(acc[6][0], sD.x, w0); ffma2(acc[7][0], sD.y, w0);
            ffma2(acc[0][1], sA.x, w1); ffma2(acc[1][1], sA.y, w1);
            ffma2(acc[2][1], sB.x, w1); ffma2(acc[3][1], sB.y, w1);
            ffma2(acc[4][1], sC.x, w1); ffma2(acc[5][1], sC.y, w1);
            ffma2(acc[6][1], sD.x, w1); ffma2(acc[7][1], sD.y, w1);
            ffma2(acc[0][2], sA.x, w2); ffma2(acc[1][2], sA.y, w2);
            ffma2(acc[2][2], sB.x, w2); ffma2(acc[3][2], sB.y, w2);
            ffma2(acc[4][2], sC.x, w2); ffma2(acc[5][2], sC.y, w2);
            ffma2(acc[6][2], sD.x, w2); ffma2(acc[7][2], sD.y, w2);
            ffma2(acc[0][3], sA.x, w3); ffma2(acc[1][3], sA.y, w3);
            ffma2(acc[2][3], sB.x, w3); ffma2(acc[3][3], sB.y, w3);
            ffma2(acc[4][3], sC.x, w3); ffma2(acc[5][3], sC.y, w3);
            ffma2(acc[6][3], sD.x, w3); ffma2(acc[7][3], sD.y, w3);
        }
    }

    float* op = g_part[blockIdx.y] + (size_t)mbase * 32;
    #pragma unroll
    for (int p = 0; p < 8; p++) {
        float2 u0 = upk(acc[p][0]), u1 = upk(acc[p][1]);
        float2 u2 = upk(acc[p][2]), u3 = upk(acc[p][3]);
        *(float4*)(op + (size_t)(m0 + 2 * p) * 32 + r0) =
            make_float4(u0.x, u1.x, u2.x, u3.x);
        *(float4*)(op + (size_t)(m0 + 2 * p + 1) * 32 + r0) =
            make_float4(u0.y, u1.y, u2.y, u3.y);
    }
}

// ---------------- kernel 5: reduce split-K partials ----------------
__global__ __launch_bounds__(256) void reduce_shared_kernel()
{
    int idx = blockIdx.x * 256 + threadIdx.x;   // float4 idx, 0..65535
    float4 s = *(const float4*)(g_part[0] + (size_t)idx * 4);
    #pragma unroll
    for (int p = 1; p < NSPLIT; p++) {
        float4 a = *(const float4*)(g_part[p] + (size_t)idx * 4);
        s.x += a.x; s.y += a.y; s.z += a.z; s.w += a.w;
    }
    *(float4*)(g_shared + (size_t)idx * 4) = s;
}

// ---------------- kernel 6: GEMM2 (proven R4 config: 128m x 64o, micro 8m x 4o)
__global__ __launch_bounds__(256) void gemm2_kernel(float* __restrict__ out)
{
    __shared__ float Ss[32 * 130];  // [k][m]
    __shared__ float Ws[32 * 68];   // [k][o]

    int tid = threadIdx.x;
    int b = blockIdx.z;
    int mbase = blockIdx.y * 128;
    int obase = blockIdx.x * 64;

    const float* sg = g_shared + ((size_t)b * 2048 + mbase) * 32;
    const float* wg = g_Wc + ((size_t)b * 4096 + obase) * 32;

    {
        int row = tid >> 1;
        int k0 = (tid & 1) * 16;
        const float* p = sg + row * 32 + k0;
        float4 s0 = *(const float4*)(p);
        float4 s1 = *(const float4*)(p + 4);
        float4 s2 = *(const float4*)(p + 8);
        float4 s3 = *(const float4*)(p + 12);
        Ss[(k0 + 0) * 130 + row] = s0.x;
        Ss[(k0 + 1) * 130 + row] = s0.y;
        Ss[(k0 + 2) * 130 + row] = s0.z;
        Ss[(k0 + 3) * 130 + row] = s0.w;
        Ss[(k0 + 4) * 130 + row] = s1.x;
        Ss[(k0 + 5) * 130 + row] = s1.y;
        Ss[(k0 + 6) * 130 + row] = s1.z;
        Ss[(k0 + 7) * 130 + row] = s1.w;
        Ss[(k0 + 8) * 130 + row] = s2.x;
        Ss[(k0 + 9) * 130 + row] = s2.y;
        Ss[(k0 + 10) * 130 + row] = s2.z;
        Ss[(k0 + 11) * 130 + row] = s2.w;
        Ss[(k0 + 12) * 130 + row] = s3.x;
        Ss[(k0 + 13) * 130 + row] = s3.y;
        Ss[(k0 + 14) * 130 + row] = s3.z;
        Ss[(k0 + 15) * 130 + row] = s3.w;
    }
    {
        int row = tid >> 2;
        int k0 = (tid & 3) * 8;
        const float* p = wg + row * 32 + k0;
        float4 w0 = *(const float4*)(p);
        float4 w1 = *(const float4*)(p + 4);
        Ws[(k0 + 0) * 68 + row] = w0.x;
        Ws[(k0 + 1) * 68 + row] = w0.y;
        Ws[(k0 + 2) * 68 + row] = w0.z;
        Ws[(k0 + 3) * 68 + row] = w0.w;
        Ws[(k0 + 4) * 68 + row] = w1.x;
        Ws[(k0 + 5) * 68 + row] = w1.y;
        Ws[(k0 + 6) * 68 + row] = w1.z;
        Ws[(k0 + 7) * 68 + row] = w1.w;
    }
    __syncthreads();

    int o0 = (tid & 15) * 4;
    int m0 = (tid >> 4) * 8;

    U64 a00 = 0, a01 = 0, a02 = 0, a03 = 0;
    U64 a10 = 0, a11 = 0, a12 = 0, a13 = 0;
    U64 a20 = 0, a21 = 0, a22 = 0, a23 = 0;
    U64 a30 = 0, a31 = 0, a32 = 0, a33 = 0;

    #pragma unroll
    for (int k = 0; k < 32; k++) {
        U64 s01 = *(const U64*)&Ss[k * 130 + m0];
        U64 s23 = *(const U64*)&Ss[k * 130 + m0 + 2];
        U64 s45 = *(const U64*)&Ss[k * 130 + m0 + 4];
        U64 s67 = *(const U64*)&Ss[k * 130 + m0 + 6];
        float4 wv = *(const float4*)&Ws[k * 68 + o0];
        U64 w0 = pk2(wv.x), w1 = pk2(wv.y), w2 = pk2(wv.z), w3 = pk2(wv.w);
        ffma2(a00, s01, w0); ffma2(a10, s23, w0); ffma2(a20, s45, w0); ffma2(a30, s67, w0);
        ffma2(a01, s01, w1); ffma2(a11, s23, w1); ffma2(a21, s45, w1); ffma2(a31, s67, w1);
        ffma2(a02, s01, w2); ffma2(a12, s23, w2); ffma2(a22, s45, w2); ffma2(a32, s67, w2);
        ffma2(a03, s01, w3); ffma2(a13, s23, w3); ffma2(a23, s45, w3); ffma2(a33, s67, w3);
    }

    float* og = out + ((size_t)(b * 2048 + mbase + m0)) * 4096 + obase + o0;
    {
        float2 p0 = upk(a00), p1 = upk(a01), p2 = upk(a02), p3 = upk(a03);
        *(float4*)(og)        = make_float4(p0.x, p1.x, p2.x, p3.x);
        *(float4*)(og + 4096) = make_float4(p0.y, p1.y, p2.y, p3.y);
    }
    {
        float2 p0 = upk(a10), p1 = upk(a11), p2 = upk(a12), p3 = upk(a13);
        *(float4*)(og + 2 * 4096) = make_float4(p0.x, p1.x, p2.x, p3.x);
        *(float4*)(og + 3 * 4096) = make_float4(p0.y, p1.y, p2.y, p3.y);
    }
    {
        float2 p0 = upk(a20), p1 = upk(a21), p2 = upk(a22), p3 = upk(a23);
        *(float4*)(og + 4 * 4096) = make_float4(p0.x, p1.x, p2.x, p3.x);
        *(float4*)(og + 5 * 4096) = make_float4(p0.y, p1.y, p2.y, p3.y);
    }
    {
        float2 p0 = upk(a30), p1 = upk(a31), p2 = upk(a32), p3 = upk(a33);
        *(float4*)(og + 6 * 4096) = make_float4(p0.x, p1.x, p2.x, p3.x);
        *(float4*)(og + 7 * 4096) = make_float4(p0.y, p1.y, p2.y, p3.y);
    }
}

// ---------------- launch ----------------
extern "C" void kernel_launch(void* const* d_in, const int* in_sizes, int n_in,
                              void* d_out, int out_size)
{
    const float* x     = (const float*)d_in[0];
    const int*   eof   = (const int*)  d_in[1];
    const float* noise = (const float*)d_in[2];
    const float* Aw    = (const float*)d_in[3];
    const float* Bw    = (const float*)d_in[4];
    const float* rw    = (const float*)d_in[5];
    const float* nw    = (const float*)d_in[6];
    float* out = (float*)d_out;

    gating_logits_kernel<<<32, 256>>>(x, eof, noise, rw, nw);
    transposeA_kernel<<<128, 256>>>(Aw);
    combine_w_kernel<<<512, 256>>>(Bw);
    gemm1_kernel<<<dim3(32, NSPLIT), 128>>>(x);
    reduce_shared_kernel<<<256, 256>>>();
    gemm2_kernel<<<dim3(64, 16, 4), 256>>>(out);
}

// round 17
// speedup vs baseline: 1.2065x; 1.1901x over previous
#include <cuda_runtime.h>
#include <cstdint>

// Shapes (fixed):
//   x[4,2048,4096] f32, eof[4] i32, noise[4,8] f32, A_w[32,4096] f32,
//   B_w[8,4096,32] f32, route_w[8,4096] f32, noise_w[8,4096] f32
//   out[4,2048,4096] f32

#define U64 unsigned long long
#define NSPLIT 16

// ---------------- scratch ----------------
__device__ float g_logits[32];
__device__ float g_At[4096 * 32];           // A transposed [k][r]
__device__ float g_Wc[4 * 4096 * 32];       // combined weight [b][o][r], 2x scaling folded
__device__ float g_part[NSPLIT][8192 * 32]; // split-K partials
__device__ float g_shared[8192 * 32];       // reduced shared activations [m][r]

// ---------------- packed f32x2 helpers ----------------
__device__ __forceinline__ U64 pk2(float v) {
    U64 r; asm("mov.b64 %0, {%1, %1};" : "=l"(r) : "f"(v)); return r;
}
__device__ __forceinline__ void ffma2(U64 &d, U64 a, U64 b) {
    asm("fma.rn.f32x2 %0, %1, %2, %0;" : "+l"(d) : "l"(a), "l"(b));
}
__device__ __forceinline__ float2 upk(U64 v) {
    float2 r; asm("mov.b64 {%0, %1}, %2;" : "=f"(r.x), "=f"(r.y) : "l"(v)); return r;
}

// ---------------- kernel 1: prep = transposeA (blocks 0..127) + gating (128..159)
__global__ __launch_bounds__(256) void prep_kernel(
    const float* __restrict__ x, const int* __restrict__ eof,
    const float* __restrict__ noise,
    const float* __restrict__ route_w, const float* __restrict__ noise_w,
    const float* __restrict__ Aw)
{
    if (blockIdx.x < 128) {
        // ---- transpose A [32,4096] -> [4096,32] (R10-proven body) ----
        __shared__ float s[32][33];
        int k0 = blockIdx.x * 32;
        int lane = threadIdx.x & 31;
        int grp  = threadIdx.x >> 5;
        #pragma unroll
        for (int i = 0; i < 4; i++) {
            int r = grp + i * 8;
            s[r][lane] = Aw[r * 4096 + k0 + lane];
        }
        __syncthreads();
        #pragma unroll
        for (int i = 0; i < 4; i++) {
            int kk = grp + i * 8;
            g_At[(k0 + kk) * 32 + lane] = s[lane][kk];
        }
    } else {
        // ---- gating logits, one block per (b,e) (R10-proven body) ----
        int be = blockIdx.x - 128;
        int b = be >> 3, e = be & 7;
        const float* xr = x + ((size_t)b * 2048 + (size_t)eof[b]) * 4096;
        const float* rw = route_w + e * 4096;
        const float* nw = noise_w + e * 4096;

        float c = 0.f, n = 0.f;
        int t = threadIdx.x;
        for (int k = t * 4; k < 4096; k += 256 * 4) {
            float4 xv = *(const float4*)(xr + k);
            float4 rv = *(const float4*)(rw + k);
            float4 nv = *(const float4*)(nw + k);
            c += xv.x * rv.x + xv.y * rv.y + xv.z * rv.z + xv.w * rv.w;
            n += xv.x * nv.x + xv.y * nv.y + xv.z * nv.z + xv.w * nv.w;
        }
        #pragma unroll
        for (int off = 16; off; off >>= 1) {
            c += __shfl_down_sync(0xFFFFFFFFu, c, off);
            n += __shfl_down_sync(0xFFFFFFFFu, n, off);
        }
        __shared__ float sc[8], sn[8];
        if ((t & 31) == 0) { sc[t >> 5] = c; sn[t >> 5] = n; }
        __syncthreads();
        if (t == 0) {
            float cs = 0.f, ns = 0.f;
            #pragma unroll
            for (int w = 0; w < 8; w++) { cs += sc[w]; ns += sn[w]; }
            float sp = (ns > 20.f) ? ns : log1pf(expf(ns));
            g_logits[be] = cs + noise[b * 8 + e] * (sp + 0.01f);
        }
    }
}

// ---------------- kernel 4: GEMM1 split-K (R10-proven, unchanged) ----------
// part[s][m][r] = sum_{k in 256-chunk} x[m][k] * At[k][r]
// grid = (64 m-tiles, NSPLIT), block = 128. BM=128, BK=32, micro 8m x 4r.
#define XST 132
__global__ __launch_bounds__(128) void gemm1_kernel(const float* __restrict__ x)
{
    __shared__ __align__(16) float Xs[32 * XST];  // [k][m], 16.9KB
    __shared__ __align__(16) float As[32 * 32];   // [k][r], 4KB

    int tid = threadIdx.x;
    int mbase = blockIdx.x * 128;
    int kbase = blockIdx.y * (4096 / NSPLIT);     // 256-k chunk = 8 tiles of 32

    int lrow  = tid >> 3;           // 0..15 ; X rows = lrow + 16*j
    int klane = tid & 7;            // thread's k set: klane + 8*i
    const float* xt = x + (size_t)(mbase + lrow) * 4096 + kbase + klane;
    const float* ag = g_At + (size_t)kbase * 32;

    // prologue: LDG tile 0 into registers (scalar, 4-sector coalesced)
    float xr[8][4];
    float4 ar[2];
    #pragma unroll
    for (int j = 0; j < 8; j++)
        #pragma unroll
        for (int i = 0; i < 4; i++)
            xr[j][i] = xt[(size_t)(16 * j) * 4096 + 8 * i];
    #pragma unroll
    for (int j = 0; j < 2; j++)
        ar[j] = *(const float4*)(ag + (tid + 128 * j) * 4);

    int m0 = (tid >> 3) * 8;        // 0..120
    int r0 = (tid & 7) * 4;         // 0..28

    U64 acc[4][4];
    #pragma unroll
    for (int p = 0; p < 4; p++)
        #pragma unroll
        for (int rr = 0; rr < 4; rr++) acc[p][rr] = 0;

    #pragma unroll 1
    for (int t = 0; t < 8; t++) {
        __syncthreads();            // previous compute done before overwrite
        // STS: conflict-free transposed stores (bank = 4*(tid&7)+lrow)
        #pragma unroll
        for (int i = 0; i < 4; i++) {
            int kk = klane + 8 * i;
            #pragma unroll
            for (int j = 0; j < 8; j++)
                Xs[kk * XST + lrow + 16 * j] = xr[j][i];
        }
        #pragma unroll
        for (int j = 0; j < 2; j++)
            *(float4*)&As[(tid + 128 * j) * 4] = ar[j];
        __syncthreads();

        // prefetch next tile (overlaps compute)
        if (t < 7) {
            const float* xt2 = xt + (t + 1) * 32;
            const float* ag2 = ag + (t + 1) * 1024;
            #pragma unroll
            for (int j = 0; j < 8; j++)
                #pragma unroll
                for (int i = 0; i < 4; i++)
                    xr[j][i] = xt2[(size_t)(16 * j) * 4096 + 8 * i];
            #pragma unroll
            for (int j = 0; j < 2; j++)
                ar[j] = *(const float4*)(ag2 + (tid + 128 * j) * 4);
        }

        #pragma unroll
        for (int k = 0; k < 32; k++) {
            ulonglong2 sA = *(const ulonglong2*)&Xs[k * XST + m0];      // m0..m0+3
            ulonglong2 sB = *(const ulonglong2*)&Xs[k * XST + m0 + 4];  // m0+4..m0+7
            float4 av = *(const float4*)&As[k * 32 + r0];
            U64 w0 = pk2(av.x), w1 = pk2(av.y), w2 = pk2(av.z), w3 = pk2(av.w);
            ffma2(acc[0][0], sA.x, w0); ffma2(acc[1][0], sA.y, w0);
            ffma2(acc[2][0], sB.x, w0); ffma2(acc[3][0], sB.y, w0);
            ffma2(acc[0][1], sA.x, w1); ffma2(acc[1][1], sA.y, w1);
            ffma2(acc[2][1], sB.x, w1); ffma2(acc[3][1], sB.y, w1);
            ffma2(acc[0][2], sA.x, w2); ffma2(acc[1][2], sA.y, w2);
            ffma2(acc[2][2], sB.x, w2); ffma2(acc[3][2], sB.y, w2);
            ffma2(acc[0][3], sA.x, w3); ffma2(acc[1][3], sA.y, w3);
            ffma2(acc[2][3], sB.x, w3); ffma2(acc[3][3], sB.y, w3);
        }
    }

    float* op = g_part[blockIdx.y] + (size_t)mbase * 32;
    #pragma unroll
    for (int p = 0; p < 4; p++) {
        float2 u0 = upk(acc[p][0]), u1 = upk(acc[p][1]);
        float2 u2 = upk(acc[p][2]), u3 = upk(acc[p][3]);
        *(float4*)(op + (size_t)(m0 + 2 * p) * 32 + r0) =
            make_float4(u0.x, u1.x, u2.x, u3.x);
        *(float4*)(op + (size_t)(m0 + 2 * p + 1) * 32 + r0) =
            make_float4(u0.y, u1.y, u2.y, u3.y);
    }
}

// ---------------- kernel: mid = reduce (blocks 0..255) + combine_w (256..767) ---
__global__ __launch_bounds__(256) void mid_kernel(const float* __restrict__ Bw)
{
    if (blockIdx.x < 256) {
        // ---- reduce split-K partials (R10-proven body) ----
        int idx = blockIdx.x * 256 + threadIdx.x;   // float4 idx, 0..65535
        float4 s = *(const float4*)(g_part[0] + (size_t)idx * 4);
        #pragma unroll
        for (int p = 1; p < NSPLIT; p++) {
            float4 a = *(const float4*)(g_part[p] + (size_t)idx * 4);
            s.x += a.x; s.y += a.y; s.z += a.z; s.w += a.w;
        }
        *(float4*)(g_shared + (size_t)idx * 4) = s;
    } else {
        // ---- combine expert weights (R10-proven body) ----
        int idx = (blockIdx.x - 256) * 256 + threadIdx.x;   // float4 index, 0..131071
        int b = idx >> 15;
        int rem4 = idx & 32767;

        float v[8];
        #pragma unroll
        for (int e = 0; e < 8; e++) v[e] = g_logits[b * 8 + e];
        int i1 = 0;
        #pragma unroll
        for (int e = 1; e < 8; e++) if (v[e] > v[i1]) i1 = e;
        int i2 = (i1 == 0) ? 1 : 0;
        #pragma unroll
        for (int e = 0; e < 8; e++) if (e != i1 && v[e] > v[i2]) i2 = e;
        float e2 = expf(v[i2] - v[i1]);
        float inv = 2.f / (1.f + e2);     // SCALING folded
        float g1 = inv;
        float g2 = e2 * inv;

        float4 p = *(const float4*)(Bw + (size_t)i1 * 131072 + (size_t)rem4 * 4);
        float4 q = *(const float4*)(Bw + (size_t)i2 * 131072 + (size_t)rem4 * 4);
        float4 acc;
        acc.x = g1 * p.x + g2 * q.x;
        acc.y = g1 * p.y + g2 * q.y;
        acc.z = g1 * p.z + g2 * q.z;
        acc.w = g1 * p.w + g2 * q.w;
        *(float4*)(g_Wc + (size_t)idx * 4) = acc;
    }
}

// ---------------- kernel 6: GEMM2 (proven R4 config: 128m x 64o, micro 8m x 4o)
__global__ __launch_bounds__(256) void gemm2_kernel(float* __restrict__ out)
{
    __shared__ float Ss[32 * 130];  // [k][m]
    __shared__ float Ws[32 * 68];   // [k][o]

    int tid = threadIdx.x;
    int b = blockIdx.z;
    int mbase = blockIdx.y * 128;
    int obase = blockIdx.x * 64;

    const float* sg = g_shared + ((size_t)b * 2048 + mbase) * 32;
    const float* wg = g_Wc + ((size_t)b * 4096 + obase) * 32;

    {
        int row = tid >> 1;
        int k0 = (tid & 1) * 16;
        const float* p = sg + row * 32 + k0;
        float4 s0 = *(const float4*)(p);
        float4 s1 = *(const float4*)(p + 4);
        float4 s2 = *(const float4*)(p + 8);
        float4 s3 = *(const float4*)(p + 12);
        Ss[(k0 + 0) * 130 + row] = s0.x;
        Ss[(k0 + 1) * 130 + row] = s0.y;
        Ss[(k0 + 2) * 130 + row] = s0.z;
        Ss[(k0 + 3) * 130 + row] = s0.w;
        Ss[(k0 + 4) * 130 + row] = s1.x;
        Ss[(k0 + 5) * 130 + row] = s1.y;
        Ss[(k0 + 6) * 130 + row] = s1.z;
        Ss[(k0 + 7) * 130 + row] = s1.w;
        Ss[(k0 + 8) * 130 + row] = s2.x;
        Ss[(k0 + 9) * 130 + row] = s2.y;
        Ss[(k0 + 10) * 130 + row] = s2.z;
        Ss[(k0 + 11) * 130 + row] = s2.w;
        Ss[(k0 + 12) * 130 + row] = s3.x;
        Ss[(k0 + 13) * 130 + row] = s3.y;
        Ss[(k0 + 14) * 130 + row] = s3.z;
        Ss[(k0 + 15) * 130 + row] = s3.w;
    }
    {
        int row = tid >> 2;
        int k0 = (tid & 3) * 8;
        const float* p = wg + row * 32 + k0;
        float4 w0 = *(const float4*)(p);
        float4 w1 = *(const float4*)(p + 4);
        Ws[(k0 + 0) * 68 + row] = w0.x;
        Ws[(k0 + 1) * 68 + row] = w0.y;
        Ws[(k0 + 2) * 68 + row] = w0.z;
        Ws[(k0 + 3) * 68 + row] = w0.w;
        Ws[(k0 + 4) * 68 + row] = w1.x;
        Ws[(k0 + 5) * 68 + row] = w1.y;
        Ws[(k0 + 6) * 68 + row] = w1.z;
        Ws[(k0 + 7) * 68 + row] = w1.w;
    }
    __syncthreads();

    int o0 = (tid & 15) * 4;
    int m0 = (tid >> 4) * 8;

    U64 a00 = 0, a01 = 0, a02 = 0, a03 = 0;
    U64 a10 = 0, a11 = 0, a12 = 0, a13 = 0;
    U64 a20 = 0, a21 = 0, a22 = 0, a23 = 0;
    U64 a30 = 0, a31 = 0, a32 = 0, a33 = 0;

    #pragma unroll
    for (int k = 0; k < 32; k++) {
        U64 s01 = *(const U64*)&Ss[k * 130 + m0];
        U64 s23 = *(const U64*)&Ss[k * 130 + m0 + 2];
        U64 s45 = *(const U64*)&Ss[k * 130 + m0 + 4];
        U64 s67 = *(const U64*)&Ss[k * 130 + m0 + 6];
        float4 wv = *(const float4*)&Ws[k * 68 + o0];
        U64 w0 = pk2(wv.x), w1 = pk2(wv.y), w2 = pk2(wv.z), w3 = pk2(wv.w);
        ffma2(a00, s01, w0); ffma2(a10, s23, w0); ffma2(a20, s45, w0); ffma2(a30, s67, w0);
        ffma2(a01, s01, w1); ffma2(a11, s23, w1); ffma2(a21, s45, w1); ffma2(a31, s67, w1);
        ffma2(a02, s01, w2); ffma2(a12, s23, w2); ffma2(a22, s45, w2); ffma2(a32, s67, w2);
        ffma2(a03, s01, w3); ffma2(a13, s23, w3); ffma2(a23, s45, w3); ffma2(a33, s67, w3);
    }

    float* og = out + ((size_t)(b * 2048 + mbase + m0)) * 4096 + obase + o0;
    {
        float2 p0 = upk(a00), p1 = upk(a01), p2 = upk(a02), p3 = upk(a03);
        *(float4*)(og)        = make_float4(p0.x, p1.x, p2.x, p3.x);
        *(float4*)(og + 4096) = make_float4(p0.y, p1.y, p2.y, p3.y);
    }
    {
        float2 p0 = upk(a10), p1 = upk(a11), p2 = upk(a12), p3 = upk(a13);
        *(float4*)(og + 2 * 4096) = make_float4(p0.x, p1.x, p2.x, p3.x);
        *(float4*)(og + 3 * 4096) = make_float4(p0.y, p1.y, p2.y, p3.y);
    }
    {
        float2 p0 = upk(a20), p1 = upk(a21), p2 = upk(a22), p3 = upk(a23);
        *(float4*)(og + 4 * 4096) = make_float4(p0.x, p1.x, p2.x, p3.x);
        *(float4*)(og + 5 * 4096) = make_float4(p0.y, p1.y, p2.y, p3.y);
    }
    {
        float2 p0 = upk(a30), p1 = upk(a31), p2 = upk(a32), p3 = upk(a33);
        *(float4*)(og + 6 * 4096) = make_float4(p0.x, p1.x, p2.x, p3.x);
        *(float4*)(og + 7 * 4096) = make_float4(p0.y, p1.y, p2.y, p3.y);
    }
}

// ---------------- launch ----------------
extern "C" void kernel_launch(void* const* d_in, const int* in_sizes, int n_in,
                              void* d_out, int out_size)
{
    const float* x     = (const float*)d_in[0];
    const int*   eof   = (const int*)  d_in[1];
    const float* noise = (const float*)d_in[2];
    const float* Aw    = (const float*)d_in[3];
    const float* Bw    = (const float*)d_in[4];
    const float* rw    = (const float*)d_in[5];
    const float* nw    = (const float*)d_in[6];
    float* out = (float*)d_out;

    prep_kernel<<<160, 256>>>(x, eof, noise, rw, nw, Aw);
    gemm1_kernel<<<dim3(64, NSPLIT), 128>>>(x);
    mid_kernel<<<768, 256>>>(Bw);
    gemm2_kernel<<<dim3(64, 16, 4), 256>>>(out);
}